// round 16
// baseline (speedup 1.0000x reference)
#include <cuda_runtime.h>
#include <cuda_fp16.h>
#include <cstdint>

// Problem constants
#define BB 4
#define SS 1024
#define DD 1024
#define HH 16
#define DH 64
#define LL 12
#define VV 32000
#define NTOK (BB*SS)        // 4096 tokens

// ---------------- scratch (static device globals; no allocs allowed) ----------
__device__ float g_x[NTOK * DD];                       // running activations fp32
__device__ __half g_hh[NTOK * DD], g_hl[NTOK * DD];    // post-LN1 hi/lo (residual pair)
__device__ __half g_th[NTOK * DD];                     // post-LN2 hi only
__device__ __half g_ah[NTOK * DD];                     // attn out hi only
__device__ __half g_xh[NTOK * DD];                     // final x hi only
__device__ __half g_qkvh[NTOK * 3 * DD];               // qkv hi only

// pure fp16 weights, all [N,K] layout
#define WA_T_OFF  0
#define WP_T_OFF  (12*3072*1024)
#define WF_T_OFF  (WP_T_OFF + 12*1024*1024)
#define WOUT_OFF  (WF_T_OFF + 12*1024*1024)
#define W_T_TOTAL (WOUT_OFF + VV*1024)
__device__ __half g_wh[W_T_TOTAL];

// ============================ helpers ==========================================
__device__ __forceinline__ uint32_t smem_u32(const void* p) {
    uint32_t a;
    asm("{ .reg .u64 t; cvta.to.shared.u64 t, %1; cvt.u32.u64 %0, t; }" : "=r"(a) : "l"(p));
    return a;
}
__device__ __forceinline__ uint32_t sw128(uint32_t o) { return o ^ ((o >> 3) & 0x70); }

__device__ __forceinline__ void cp16(uint32_t dst, const void* src) {
    asm volatile("cp.async.cg.shared.global [%0], [%1], 16;" :: "r"(dst), "l"(src) : "memory");
}
#define CP_COMMIT() asm volatile("cp.async.commit_group;" ::: "memory")
#define CP_WAIT0()  asm volatile("cp.async.wait_group 0;" ::: "memory")
#define CP_WAIT1()  asm volatile("cp.async.wait_group 1;" ::: "memory")

__device__ __forceinline__ void ldsm_x4(uint32_t* r, uint32_t addr) {
    asm volatile("ldmatrix.sync.aligned.m8n8.x4.shared.b16 {%0,%1,%2,%3}, [%4];"
        : "=r"(r[0]), "=r"(r[1]), "=r"(r[2]), "=r"(r[3]) : "r"(addr));
}
__device__ __forceinline__ void ldsm_x4_t(uint32_t* r, uint32_t addr) {
    asm volatile("ldmatrix.sync.aligned.m8n8.x4.trans.shared.b16 {%0,%1,%2,%3}, [%4];"
        : "=r"(r[0]), "=r"(r[1]), "=r"(r[2]), "=r"(r[3]) : "r"(addr));
}
__device__ __forceinline__ void mma_f16(float* d, const uint32_t* a, const uint32_t* b) {
    asm volatile(
        "mma.sync.aligned.m16n8k16.row.col.f32.f16.f16.f32 "
        "{%0,%1,%2,%3}, {%4,%5,%6,%7}, {%8,%9}, {%0,%1,%2,%3};"
        : "+f"(d[0]), "+f"(d[1]), "+f"(d[2]), "+f"(d[3])
        : "r"(a[0]), "r"(a[1]), "r"(a[2]), "r"(a[3]), "r"(b[0]), "r"(b[1]));
}

__device__ __forceinline__ uint32_t packh2(__half a, __half b) {
    __half2 h = __halves2half2(a, b);
    return *(uint32_t*)&h;
}
__device__ __forceinline__ void split2h(float x, float y, uint32_t& hi, uint32_t& lo) {
    __half hx = __float2half_rn(x), hy = __float2half_rn(y);
    hi = packh2(hx, hy);
    lo = packh2(__float2half_rn(x - __half2float(hx)),
                __float2half_rn(y - __half2float(hy)));
}
__device__ __forceinline__ uint32_t pack2h(float x, float y) {
    return packh2(__float2half_rn(x), __float2half_rn(y));
}
__device__ __forceinline__ float h2sum(uint32_t hi, uint32_t lo, int idx) {
    __half2 h = *(__half2*)&hi;
    __half2 l = *(__half2*)&lo;
    return idx ? (__half2float(__high2half(h)) + __half2float(__high2half(l)))
               : (__half2float(__low2half(h))  + __half2float(__low2half(l)));
}

// ============================ embedding / LN ===================================
__global__ void embed_kernel(const int* __restrict__ X, const float* __restrict__ emb,
                             const float* __restrict__ pe, float* __restrict__ x)
{
    int m = blockIdx.x;
    int t = threadIdx.x;
    int tok = X[m];
    int b = m >> 10;
    float4 e = ((const float4*)(emb + (size_t)tok * DD))[t];
    float4 p = ((const float4*)(pe  + (size_t)b   * DD))[t];
    float4 o;
    o.x = e.x * 32.0f + p.x;  o.y = e.y * 32.0f + p.y;
    o.z = e.z * 32.0f + p.z;  o.w = e.w * 32.0f + p.w;
    ((float4*)(x + (size_t)m * DD))[t] = o;
}

template<bool WRITE_LO>
__global__ void ln_h_kernel(const float* __restrict__ x, const float* __restrict__ g,
                            const float* __restrict__ b,
                            __half* __restrict__ Yh, __half* __restrict__ Yl)
{
    int row = blockIdx.x;
    int t = threadIdx.x;
    float4 v = ((const float4*)(x + (size_t)row * DD))[t];
    float s  = v.x + v.y + v.z + v.w;
    float ss = v.x*v.x + v.y*v.y + v.z*v.z + v.w*v.w;
    #pragma unroll
    for (int o = 16; o; o >>= 1) {
        s  += __shfl_xor_sync(0xFFFFFFFFu, s,  o);
        ss += __shfl_xor_sync(0xFFFFFFFFu, ss, o);
    }
    __shared__ float sm[16];
    __shared__ float s_mu, s_r;
    int w = t >> 5;
    if ((t & 31) == 0) { sm[w] = s; sm[8 + w] = ss; }
    __syncthreads();
    if (t == 0) {
        float a = 0.f, c = 0.f;
        #pragma unroll
        for (int i = 0; i < 8; i++) { a += sm[i]; c += sm[8 + i]; }
        float mu  = a * (1.0f / DD);
        float var = c * (1.0f / DD) - mu * mu;
        s_mu = mu;
        s_r  = rsqrtf(var + 1e-5f);
    }
    __syncthreads();
    float mu = s_mu, r = s_r;
    float4 gv = ((const float4*)g)[t];
    float4 bv = ((const float4*)b)[t];
    float4 o;
    o.x = (v.x - mu) * r * gv.x + bv.x;
    o.y = (v.y - mu) * r * gv.y + bv.y;
    o.z = (v.z - mu) * r * gv.z + bv.z;
    o.w = (v.w - mu) * r * gv.w + bv.w;
    if (WRITE_LO) {
        uint32_t h01, h23, l01, l23;
        split2h(o.x, o.y, h01, l01);
        split2h(o.z, o.w, h23, l23);
        ((uint2*)(Yh + (size_t)row * DD))[t] = make_uint2(h01, h23);
        ((uint2*)(Yl + (size_t)row * DD))[t] = make_uint2(l01, l23);
    } else {
        ((uint2*)(Yh + (size_t)row * DD))[t] =
            make_uint2(pack2h(o.x, o.y), pack2h(o.z, o.w));
    }
}

// ================== weight prep ===============================================
__global__ void transpose_tohalf_kernel(const float* __restrict__ W,
                                        __half* __restrict__ Wh,
                                        int K, int N)
{
    __shared__ float t[32][33];
    int l = blockIdx.z;
    W  += (size_t)l * K * N;
    Wh += (size_t)l * N * K;
    int n0 = blockIdx.x * 32, k0 = blockIdx.y * 32;
    int tx = threadIdx.x, ty = threadIdx.y;
    #pragma unroll
    for (int i = 0; i < 4; i++)
        t[ty + 8*i][tx] = W[(size_t)(k0 + ty + 8*i) * N + n0 + tx];
    __syncthreads();
    #pragma unroll
    for (int i = 0; i < 4; i++) {
        Wh[(size_t)(n0 + ty + 8*i) * K + k0 + tx] = __float2half_rn(t[tx][ty + 8*i]);
    }
}

__global__ void tohalf_kernel(const float* __restrict__ W, __half* __restrict__ Wh)
{
    size_t i = (size_t)blockIdx.x * blockDim.x + threadIdx.x;
    float4 v = ((const float4*)W)[i];
    ((uint2*)Wh)[i] = make_uint2(pack2h(v.x, v.y), pack2h(v.z, v.w));
}

// ====================== HMMA fp16 GEMM (1-term, 3-stage) =======================
// C[M,N] = Ah[M,K] @ Bh^T[N,K], fp32 accum. OUTS: fp16 hi output.
// 128x128 tile, K-step 64, 256 threads (8 warps, 4M x 2N), 3-stage cp.async
// (prefetch distance 2, wait_group 1 steady state), 2 CTAs/SM.
#define A_HI 0
#define B_HI 16384
#define STAGE_BYTES 32768
#define GEMM_DSMEM (3*STAGE_BYTES + 1024)

template<int RESMODE, bool OUTS>
__global__ void __launch_bounds__(256, 2)
gemm_hh(const __half* __restrict__ Ah,
        const __half* __restrict__ Bh,
        const float* __restrict__ bias,
        const float* __restrict__ resf,
        const __half* __restrict__ resh, const __half* __restrict__ resl,
        float* __restrict__ C,
        __half* __restrict__ Ch,
        int M, int N, int K)
{
    extern __shared__ char dsm[];
    uint32_t raw = smem_u32(dsm);
    uint32_t tb = (raw + 1023u) & ~1023u;

    const int tid = threadIdx.x;
    const int l   = tid & 31;
    const int wid = tid >> 5;
    const int wm  = (wid & 3) * 32;
    const int wn  = (wid >> 2) * 64;
    const int bm  = blockIdx.x * 128;
    const int bn  = blockIdx.y * 128;

    const uint32_t hi16 = (uint32_t)((l >> 4) * 16);
    uint32_t abase[2], amask[2], bbase[4], bmask[4];
    #pragma unroll
    for (int mi = 0; mi < 2; mi++) {
        uint32_t r = (uint32_t)(wm + mi * 16 + (l & 15));
        abase[mi] = r * 128;
        amask[mi] = (r & 7) << 4;
    }
    #pragma unroll
    for (int nb = 0; nb < 4; nb++) {
        uint32_t r = (uint32_t)(wn + nb * 16 + (l & 15));
        bbase[nb] = r * 128;
        bmask[nb] = (r & 7) << 4;
    }

    float d[2][8][4];
    #pragma unroll
    for (int i = 0; i < 2; i++)
        #pragma unroll
        for (int j = 0; j < 8; j++)
            #pragma unroll
            for (int k = 0; k < 4; k++) d[i][j][k] = 0.f;

    const int nt = K >> 6;

    #define LOAD_T(stg, k0) { \
        uint32_t base = tb + (stg) * STAGE_BYTES; \
        _Pragma("unroll") \
        for (int i = 0; i < 4; i++) { \
            int c = tid + i * 256; int r = c >> 3, s = c & 7; \
            uint32_t off = sw128((uint32_t)(r * 128 + s * 16)); \
            size_t ga = (size_t)(bm + r) * K + (k0) + s * 8; \
            size_t gb = (size_t)(bn + r) * K + (k0) + s * 8; \
            cp16(base + A_HI + off, Ah + ga); \
            cp16(base + B_HI + off, Bh + gb); } }

    LOAD_T(0, 0);  CP_COMMIT();
    LOAD_T(1, 64); CP_COMMIT();

    for (int t = 0; t < nt; t++) {
        if (t + 1 < nt) { CP_WAIT1(); } else { CP_WAIT0(); }
        __syncthreads();            // all warps done with stage t-1 (buffer (t+2)%3)
        if (t + 2 < nt) {
            LOAD_T((t + 2) % 3, (t + 2) << 6);
            CP_COMMIT();
        }
        {
            uint32_t sb = tb + (uint32_t)(t % 3) * STAGE_BYTES;
            #pragma unroll
            for (int ks = 0; ks < 4; ks++) {
                const uint32_t ko = (uint32_t)(ks * 32);
                uint32_t aH[2][4];
                #pragma unroll
                for (int mi = 0; mi < 2; mi++) {
                    uint32_t ao = abase[mi] + ((hi16 + ko) ^ amask[mi]);
                    ldsm_x4(aH[mi], sb + A_HI + ao);
                }
                uint32_t bH[8][2];
                #pragma unroll
                for (int nb = 0; nb < 4; nb++) {
                    uint32_t bo = bbase[nb] + ((hi16 + ko) ^ bmask[nb]);
                    uint32_t r4[4];
                    ldsm_x4(r4, sb + B_HI + bo);
                    bH[2*nb][0] = r4[0]; bH[2*nb][1] = r4[2];
                    bH[2*nb+1][0] = r4[1]; bH[2*nb+1][1] = r4[3];
                }
                #pragma unroll
                for (int nj = 0; nj < 8; nj++) {
                    #pragma unroll
                    for (int mi = 0; mi < 2; mi++)
                        mma_f16(d[mi][nj], aH[mi], bH[nj]);
                }
            }
        }
    }

    // ---- epilogue ----
    #pragma unroll
    for (int mi = 0; mi < 2; mi++) {
        #pragma unroll
        for (int half = 0; half < 2; half++) {
            int row = bm + wm + mi * 16 + half * 8 + (l >> 2);
            #pragma unroll
            for (int nj = 0; nj < 8; nj++) {
                int col = bn + wn + nj * 8 + 2 * (l & 3);
                float v0 = d[mi][nj][2 * half];
                float v1 = d[mi][nj][2 * half + 1];
                if (bias) { v0 += bias[col]; v1 += bias[col + 1]; }
                size_t ri = (size_t)row * N + col;
                if (RESMODE == 1) {
                    float2 r2 = *(const float2*)&resf[ri];
                    v0 += r2.x; v1 += r2.y;
                } else if (RESMODE == 2) {
                    uint32_t rh = *(const uint32_t*)&resh[ri];
                    uint32_t rl = *(const uint32_t*)&resl[ri];
                    v0 += h2sum(rh, rl, 0);
                    v1 += h2sum(rh, rl, 1);
                }
                if (OUTS) {
                    *(uint32_t*)&Ch[ri] = pack2h(v0, v1);
                } else {
                    float2 o; o.x = v0; o.y = v1;
                    *(float2*)&C[ri] = o;
                }
            }
        }
    }
}

// ================== HMMA flash attention (fp16, 3-stage K/V) ===================
// Q, K, V all hi-only. 3 KV buffers (prefetch distance 2), 2 CTAs/SM.
#define AQ_HI 0
#define AKV_OFF 16384
#define AKV_BUF 16384           // [Kh 8K][Vh 8K]
#define ATTN_DSMEM (AKV_OFF + 3*AKV_BUF + 1024)

__global__ void __launch_bounds__(256, 2)
attn_mma(const __half* __restrict__ qh, __half* __restrict__ oh)
{
    extern __shared__ char dsm[];
    uint32_t raw = smem_u32(dsm);
    uint32_t tb = (raw + 1023u) & ~1023u;

    const int tid = threadIdx.x;
    const int l   = tid & 31;
    const int w   = tid >> 5;
    const int bh  = blockIdx.y;
    const int b   = bh >> 4;
    const int h   = bh & 15;
    const int q0  = blockIdx.x * 128;
    const size_t hoff = (size_t)h * DH;

    // Q load batched with KV tile 0 into cp.async group 0
    #pragma unroll
    for (int i = 0; i < 4; i++) {
        int lin = tid + i * 256;
        int row = lin >> 3, ch = lin & 7;
        const __half* src = qh + (size_t)(b * SS + q0 + row) * (3 * DD) + hoff + ch * 8;
        cp16(tb + AQ_HI + sw128((uint32_t)(row * 128 + ch * 16)), src);
    }
    // K tile 8KB + V tile 8KB = 1024 x 16B slots -> 4 iterations of 256 threads
    #define LOAD_KV(t, buf) { \
        _Pragma("unroll") \
        for (int i = 0; i < 4; i++) { \
            int lin = tid + i * 256; \
            int kv = lin >> 9, row = (lin >> 3) & 63, ch = lin & 7; \
            const __half* src = qh \
                + (size_t)(b * SS + (t) * 64 + row) * (3 * DD) \
                + (kv ? 2 * DD : DD) + hoff + ch * 8; \
            cp16(tb + AKV_OFF + (buf) * AKV_BUF + kv * 8192 \
                 + sw128((uint32_t)(row * 128 + ch * 16)), src); } }

    LOAD_KV(0, 0); CP_COMMIT();
    LOAD_KV(1, 1); CP_COMMIT();

    float od[8][4];
    #pragma unroll
    for (int j = 0; j < 8; j++)
        #pragma unroll
        for (int k = 0; k < 4; k++) od[j][k] = 0.f;
    float m0 = -1e30f, m1 = -1e30f, l0 = 0.f, l1 = 0.f;

    uint32_t aQh[4][4];
    const uint32_t qrow = (uint32_t)(w * 16 + (l & 15));
    const uint32_t qmask = (qrow & 7) << 4;
    const uint32_t hi16 = (uint32_t)((l >> 4) * 16);

    for (int t = 0; t < 16; t++) {
        if (t + 1 < 16) { CP_WAIT1(); } else { CP_WAIT0(); }
        __syncthreads();            // all warps done with tile t-1 (buffer (t+2)%3)
        if (t + 2 < 16) { LOAD_KV(t + 2, (t + 2) % 3); CP_COMMIT(); }
        if (t == 0) {
            #pragma unroll
            for (int ks = 0; ks < 4; ks++) {
                uint32_t off = qrow * 128 + ((hi16 + ks * 32) ^ qmask);
                ldsm_x4(aQh[ks], tb + AQ_HI + off);
            }
        }
        const uint32_t sK = tb + AKV_OFF + (uint32_t)(t % 3) * AKV_BUF;
        const uint32_t sV = sK + 8192;

        float sc[8][4];
        #pragma unroll
        for (int j = 0; j < 8; j++)
            #pragma unroll
            for (int k = 0; k < 4; k++) sc[j][k] = 0.f;
        #pragma unroll
        for (int ks = 0; ks < 4; ks++) {
            #pragma unroll
            for (int nb = 0; nb < 4; nb++) {
                uint32_t row = (uint32_t)(nb * 16 + (l & 15));
                uint32_t off = row * 128 + ((hi16 + ks * 32) ^ ((row & 7) << 4));
                uint32_t r4[4];
                ldsm_x4(r4, sK + off);
                uint32_t bh0[2] = {r4[0], r4[2]}, bh1[2] = {r4[1], r4[3]};
                mma_f16(sc[2*nb],   aQh[ks], bh0);
                mma_f16(sc[2*nb+1], aQh[ks], bh1);
            }
        }

        float nm0 = m0, nm1 = m1;
        #pragma unroll
        for (int nj = 0; nj < 8; nj++) {
            nm0 = fmaxf(nm0, fmaxf(sc[nj][0], sc[nj][1]));
            nm1 = fmaxf(nm1, fmaxf(sc[nj][2], sc[nj][3]));
        }
        nm0 = fmaxf(nm0, __shfl_xor_sync(0xFFFFFFFFu, nm0, 1));
        nm0 = fmaxf(nm0, __shfl_xor_sync(0xFFFFFFFFu, nm0, 2));
        nm1 = fmaxf(nm1, __shfl_xor_sync(0xFFFFFFFFu, nm1, 1));
        nm1 = fmaxf(nm1, __shfl_xor_sync(0xFFFFFFFFu, nm1, 2));
        float cor0 = __expf(m0 - nm0), cor1 = __expf(m1 - nm1);
        m0 = nm0; m1 = nm1;
        float rs0 = 0.f, rs1 = 0.f;
        #pragma unroll
        for (int nj = 0; nj < 8; nj++) {
            sc[nj][0] = __expf(sc[nj][0] - nm0);
            sc[nj][1] = __expf(sc[nj][1] - nm0);
            sc[nj][2] = __expf(sc[nj][2] - nm1);
            sc[nj][3] = __expf(sc[nj][3] - nm1);
            rs0 += sc[nj][0] + sc[nj][1];
            rs1 += sc[nj][2] + sc[nj][3];
        }
        rs0 += __shfl_xor_sync(0xFFFFFFFFu, rs0, 1);
        rs0 += __shfl_xor_sync(0xFFFFFFFFu, rs0, 2);
        rs1 += __shfl_xor_sync(0xFFFFFFFFu, rs1, 1);
        rs1 += __shfl_xor_sync(0xFFFFFFFFu, rs1, 2);
        l0 = l0 * cor0 + rs0;
        l1 = l1 * cor1 + rs1;
        #pragma unroll
        for (int nj = 0; nj < 8; nj++) {
            od[nj][0] *= cor0; od[nj][1] *= cor0;
            od[nj][2] *= cor1; od[nj][3] *= cor1;
        }

        #pragma unroll
        for (int kj = 0; kj < 4; kj++) {
            uint32_t aPh[4];
            aPh[0] = pack2h(sc[2*kj][0],   sc[2*kj][1]);
            aPh[1] = pack2h(sc[2*kj][2],   sc[2*kj][3]);
            aPh[2] = pack2h(sc[2*kj+1][0], sc[2*kj+1][1]);
            aPh[3] = pack2h(sc[2*kj+1][2], sc[2*kj+1][3]);
            const uint32_t mat = (uint32_t)(l >> 3);
            const uint32_t vrow = (uint32_t)(kj * 16 + (mat & 1) * 8 + (l & 7));
            const uint32_t vmask = (vrow & 7) << 4;
            #pragma unroll
            for (int pp = 0; pp < 4; pp++) {
                uint32_t off = vrow * 128 + (((uint32_t)(pp * 32) + (mat >> 1) * 16) ^ vmask);
                uint32_t rh[4];
                ldsm_x4_t(rh, sV + off);
                uint32_t b0h[2] = {rh[0], rh[1]}, b1h[2] = {rh[2], rh[3]};
                mma_f16(od[2*pp],   aPh, b0h);
                mma_f16(od[2*pp+1], aPh, b1h);
            }
        }
    }

    float inv0 = 1.0f / l0, inv1 = 1.0f / l1;
    int row0 = q0 + w * 16 + (l >> 2);
    #pragma unroll
    for (int nj = 0; nj < 8; nj++) {
        int col = (int)hoff + nj * 8 + 2 * (l & 3);
        size_t ri0 = (size_t)(b * SS + row0) * DD + col;
        size_t ri1 = (size_t)(b * SS + row0 + 8) * DD + col;
        *(uint32_t*)&oh[ri0] = pack2h(od[nj][0] * inv0, od[nj][1] * inv0);
        *(uint32_t*)&oh[ri1] = pack2h(od[nj][2] * inv1, od[nj][3] * inv1);
    }
}

// ---------------- launch -------------------------------------------------------
extern "C" void kernel_launch(void* const* d_in, const int* in_sizes, int n_in,
                              void* d_out, int out_size)
{
    const int*   X     = (const int*)  d_in[0];
    const float* emb   = (const float*)d_in[1];
    const float* pe    = (const float*)d_in[2];
    const float* ln1_g = (const float*)d_in[3];
    const float* ln1_b = (const float*)d_in[4];
    const float* wa    = (const float*)d_in[5];
    const float* ba    = (const float*)d_in[6];
    const float* wp    = (const float*)d_in[7];
    const float* bp    = (const float*)d_in[8];
    const float* ln2_g = (const float*)d_in[9];
    const float* ln2_b = (const float*)d_in[10];
    const float* wf    = (const float*)d_in[11];
    const float* bf    = (const float*)d_in[12];
    const float* wout  = (const float*)d_in[13];
    float* logits = (float*)d_out;

    float *x;
    __half *wh, *qkvh, *hh, *hl, *th, *ah, *xh;
    cudaGetSymbolAddress((void**)&x,    g_x);
    cudaGetSymbolAddress((void**)&wh,   g_wh);
    cudaGetSymbolAddress((void**)&qkvh, g_qkvh);
    cudaGetSymbolAddress((void**)&hh,   g_hh);
    cudaGetSymbolAddress((void**)&hl,   g_hl);
    cudaGetSymbolAddress((void**)&th,   g_th);
    cudaGetSymbolAddress((void**)&ah,   g_ah);
    cudaGetSymbolAddress((void**)&xh,   g_xh);

    cudaFuncSetAttribute(gemm_hh<0,true>,  cudaFuncAttributeMaxDynamicSharedMemorySize, GEMM_DSMEM);
    cudaFuncSetAttribute(gemm_hh<2,false>, cudaFuncAttributeMaxDynamicSharedMemorySize, GEMM_DSMEM);
    cudaFuncSetAttribute(gemm_hh<1,false>, cudaFuncAttributeMaxDynamicSharedMemorySize, GEMM_DSMEM);
    cudaFuncSetAttribute(gemm_hh<0,false>, cudaFuncAttributeMaxDynamicSharedMemorySize, GEMM_DSMEM);
    cudaFuncSetAttribute(attn_mma, cudaFuncAttributeMaxDynamicSharedMemorySize, ATTN_DSMEM);

    // weight prep (per replay, HBM-stream bound; fp16 hi only)
    transpose_tohalf_kernel<<<dim3(3*DD/32, DD/32, LL), dim3(32,8)>>>(
        wa, wh + WA_T_OFF, DD, 3*DD);
    transpose_tohalf_kernel<<<dim3(DD/32, DD/32, LL), dim3(32,8)>>>(
        wp, wh + WP_T_OFF, DD, DD);
    transpose_tohalf_kernel<<<dim3(DD/32, DD/32, LL), dim3(32,8)>>>(
        wf, wh + WF_T_OFF, DD, DD);
    tohalf_kernel<<<(VV*1024/4)/256, 256>>>(wout, wh + WOUT_OFF);

    embed_kernel<<<NTOK, 256>>>(X, emb, pe, x);

    for (int i = 0; i < LL; i++) {
        const float* ba_i = ba + (size_t)i * 3 * DD;
        const float* bp_i = bp + (size_t)i * DD;
        const float* bf_i = bf + (size_t)i * DD;
        const __half* wa_h = wh + WA_T_OFF + (size_t)i * 3*DD * DD;
        const __half* wp_h = wh + WP_T_OFF + (size_t)i * DD * DD;
        const __half* wf_h = wh + WF_T_OFF + (size_t)i * DD * DD;

        ln_h_kernel<true><<<NTOK, 256>>>(x, ln1_g + (size_t)i * DD, ln1_b + (size_t)i * DD, hh, hl);
        gemm_hh<0,true><<<dim3(NTOK/128, 3*DD/128), 256, GEMM_DSMEM>>>(
            hh, wa_h, ba_i, nullptr, nullptr, nullptr,
            nullptr, qkvh, NTOK, 3*DD, DD);
        attn_mma<<<dim3(SS/128, BB*HH), 256, ATTN_DSMEM>>>(qkvh, ah);
        gemm_hh<2,false><<<dim3(NTOK/128, DD/128), 256, GEMM_DSMEM>>>(
            ah, wp_h, bp_i, nullptr, hh, hl,
            x, nullptr, NTOK, DD, DD);
        ln_h_kernel<false><<<NTOK, 256>>>(x, ln2_g + (size_t)i * DD, ln2_b + (size_t)i * DD, th, nullptr);
        gemm_hh<1,false><<<dim3(NTOK/128, DD/128), 256, GEMM_DSMEM>>>(
            th, wf_h, bf_i, x, nullptr, nullptr,
            x, nullptr, NTOK, DD, DD);
    }

    // logits = x @ wout^T
    tohalf_kernel<<<(NTOK*DD/4)/256, 256>>>(x, xh);
    gemm_hh<0,false><<<dim3(NTOK/128, VV/128), 256, GEMM_DSMEM>>>(
        xh, wh + WOUT_OFF, nullptr, nullptr, nullptr, nullptr,
        logits, nullptr, NTOK, VV, DD);
    (void)in_sizes; (void)n_in; (void)out_size;
}

// round 17
// speedup vs baseline: 1.0080x; 1.0080x over previous
#include <cuda_runtime.h>
#include <cuda_fp16.h>
#include <cstdint>

// Problem constants
#define BB 4
#define SS 1024
#define DD 1024
#define HH 16
#define DH 64
#define LL 12
#define VV 32000
#define NTOK (BB*SS)        // 4096 tokens

// ---------------- scratch (static device globals; no allocs allowed) ----------
__device__ float g_x[NTOK * DD];                       // running activations fp32
__device__ __half g_hh[NTOK * DD], g_hl[NTOK * DD];    // post-LN1 hi/lo (residual pair)
__device__ __half g_th[NTOK * DD];                     // post-LN2 hi only
__device__ __half g_ah[NTOK * DD];                     // attn out hi only
__device__ __half g_xh[NTOK * DD];                     // final x hi only
__device__ __half g_qkvh[NTOK * 3 * DD];               // qkv hi only

// pure fp16 weights, all [N,K] layout
#define WA_T_OFF  0
#define WP_T_OFF  (12*3072*1024)
#define WF_T_OFF  (WP_T_OFF + 12*1024*1024)
#define WOUT_OFF  (WF_T_OFF + 12*1024*1024)
#define W_T_TOTAL (WOUT_OFF + VV*1024)
__device__ __half g_wh[W_T_TOTAL];

// ============================ helpers ==========================================
__device__ __forceinline__ uint32_t smem_u32(const void* p) {
    uint32_t a;
    asm("{ .reg .u64 t; cvta.to.shared.u64 t, %1; cvt.u32.u64 %0, t; }" : "=r"(a) : "l"(p));
    return a;
}
__device__ __forceinline__ uint32_t sw128(uint32_t o) { return o ^ ((o >> 3) & 0x70); }

__device__ __forceinline__ void cp16(uint32_t dst, const void* src) {
    asm volatile("cp.async.cg.shared.global [%0], [%1], 16;" :: "r"(dst), "l"(src) : "memory");
}
#define CP_COMMIT() asm volatile("cp.async.commit_group;" ::: "memory")
#define CP_WAIT0()  asm volatile("cp.async.wait_group 0;" ::: "memory")

__device__ __forceinline__ void ldsm_x4(uint32_t* r, uint32_t addr) {
    asm volatile("ldmatrix.sync.aligned.m8n8.x4.shared.b16 {%0,%1,%2,%3}, [%4];"
        : "=r"(r[0]), "=r"(r[1]), "=r"(r[2]), "=r"(r[3]) : "r"(addr));
}
__device__ __forceinline__ void ldsm_x4_t(uint32_t* r, uint32_t addr) {
    asm volatile("ldmatrix.sync.aligned.m8n8.x4.trans.shared.b16 {%0,%1,%2,%3}, [%4];"
        : "=r"(r[0]), "=r"(r[1]), "=r"(r[2]), "=r"(r[3]) : "r"(addr));
}
__device__ __forceinline__ void mma_f16(float* d, const uint32_t* a, const uint32_t* b) {
    asm volatile(
        "mma.sync.aligned.m16n8k16.row.col.f32.f16.f16.f32 "
        "{%0,%1,%2,%3}, {%4,%5,%6,%7}, {%8,%9}, {%0,%1,%2,%3};"
        : "+f"(d[0]), "+f"(d[1]), "+f"(d[2]), "+f"(d[3])
        : "r"(a[0]), "r"(a[1]), "r"(a[2]), "r"(a[3]), "r"(b[0]), "r"(b[1]));
}

__device__ __forceinline__ uint32_t packh2(__half a, __half b) {
    __half2 h = __halves2half2(a, b);
    return *(uint32_t*)&h;
}
__device__ __forceinline__ void split2h(float x, float y, uint32_t& hi, uint32_t& lo) {
    __half hx = __float2half_rn(x), hy = __float2half_rn(y);
    hi = packh2(hx, hy);
    lo = packh2(__float2half_rn(x - __half2float(hx)),
                __float2half_rn(y - __half2float(hy)));
}
__device__ __forceinline__ uint32_t pack2h(float x, float y) {
    return packh2(__float2half_rn(x), __float2half_rn(y));
}
__device__ __forceinline__ float h2sum(uint32_t hi, uint32_t lo, int idx) {
    __half2 h = *(__half2*)&hi;
    __half2 l = *(__half2*)&lo;
    return idx ? (__half2float(__high2half(h)) + __half2float(__high2half(l)))
               : (__half2float(__low2half(h))  + __half2float(__low2half(l)));
}

// ============================ embedding / LN ===================================
__global__ void embed_kernel(const int* __restrict__ X, const float* __restrict__ emb,
                             const float* __restrict__ pe, float* __restrict__ x)
{
    int m = blockIdx.x;
    int t = threadIdx.x;
    int tok = X[m];
    int b = m >> 10;
    float4 e = ((const float4*)(emb + (size_t)tok * DD))[t];
    float4 p = ((const float4*)(pe  + (size_t)b   * DD))[t];
    float4 o;
    o.x = e.x * 32.0f + p.x;  o.y = e.y * 32.0f + p.y;
    o.z = e.z * 32.0f + p.z;  o.w = e.w * 32.0f + p.w;
    ((float4*)(x + (size_t)m * DD))[t] = o;
}

// warp-per-row layernorm: 8 rows per 256-thread block, shuffle-only reduction
template<bool WRITE_LO>
__global__ void ln_w_kernel(const float* __restrict__ x, const float* __restrict__ g,
                            const float* __restrict__ b,
                            __half* __restrict__ Yh, __half* __restrict__ Yl)
{
    const int row  = (blockIdx.x * blockDim.x + threadIdx.x) >> 5;
    const int lane = threadIdx.x & 31;
    const float4* xr = (const float4*)(x + (size_t)row * DD);
    float4 v[8];
    float s = 0.f, ss = 0.f;
    #pragma unroll
    for (int i = 0; i < 8; i++) {
        v[i] = xr[lane + 32 * i];
        s  += v[i].x + v[i].y + v[i].z + v[i].w;
        ss += v[i].x*v[i].x + v[i].y*v[i].y + v[i].z*v[i].z + v[i].w*v[i].w;
    }
    #pragma unroll
    for (int o = 16; o; o >>= 1) {
        s  += __shfl_xor_sync(0xFFFFFFFFu, s,  o);
        ss += __shfl_xor_sync(0xFFFFFFFFu, ss, o);
    }
    float mu  = s * (1.0f / DD);
    float var = ss * (1.0f / DD) - mu * mu;
    float r   = rsqrtf(var + 1e-5f);
    const float4* gp = (const float4*)g;
    const float4* bp = (const float4*)b;
    #pragma unroll
    for (int i = 0; i < 8; i++) {
        float4 gv = gp[lane + 32 * i];
        float4 bv = bp[lane + 32 * i];
        float4 o;
        o.x = (v[i].x - mu) * r * gv.x + bv.x;
        o.y = (v[i].y - mu) * r * gv.y + bv.y;
        o.z = (v[i].z - mu) * r * gv.z + bv.z;
        o.w = (v[i].w - mu) * r * gv.w + bv.w;
        if (WRITE_LO) {
            uint32_t h01, h23, l01, l23;
            split2h(o.x, o.y, h01, l01);
            split2h(o.z, o.w, h23, l23);
            ((uint2*)(Yh + (size_t)row * DD))[lane + 32 * i] = make_uint2(h01, h23);
            ((uint2*)(Yl + (size_t)row * DD))[lane + 32 * i] = make_uint2(l01, l23);
        } else {
            ((uint2*)(Yh + (size_t)row * DD))[lane + 32 * i] =
                make_uint2(pack2h(o.x, o.y), pack2h(o.z, o.w));
        }
    }
}

// ================== weight prep ===============================================
__global__ void transpose_tohalf_kernel(const float* __restrict__ W,
                                        __half* __restrict__ Wh,
                                        int K, int N)
{
    __shared__ float t[32][33];
    int l = blockIdx.z;
    W  += (size_t)l * K * N;
    Wh += (size_t)l * N * K;
    int n0 = blockIdx.x * 32, k0 = blockIdx.y * 32;
    int tx = threadIdx.x, ty = threadIdx.y;
    #pragma unroll
    for (int i = 0; i < 4; i++)
        t[ty + 8*i][tx] = W[(size_t)(k0 + ty + 8*i) * N + n0 + tx];
    __syncthreads();
    #pragma unroll
    for (int i = 0; i < 4; i++) {
        Wh[(size_t)(n0 + ty + 8*i) * K + k0 + tx] = __float2half_rn(t[tx][ty + 8*i]);
    }
}

__global__ void tohalf_kernel(const float* __restrict__ W, __half* __restrict__ Wh)
{
    size_t i = (size_t)blockIdx.x * blockDim.x + threadIdx.x;
    float4 v = ((const float4*)W)[i];
    ((uint2*)Wh)[i] = make_uint2(pack2h(v.x, v.y), pack2h(v.z, v.w));
}

// ====================== HMMA fp16 GEMM (1-term, 2-stage) =======================
// C[M,N] = Ah[M,K] @ Bh^T[N,K], fp32 accum. OUTS: fp16 hi output.
// 128x128 tile, K-step 64, 256 threads (8 warps, 4M x 2N), 2-stage, 2 CTAs/SM,
// single sync/iter (prefetch t+1 before compute t).
#define A_HI 0
#define B_HI 16384
#define STAGE_BYTES 32768
#define GEMM_DSMEM (2*STAGE_BYTES + 1024)

template<int RESMODE, bool OUTS>
__global__ void __launch_bounds__(256, 2)
gemm_hh(const __half* __restrict__ Ah,
        const __half* __restrict__ Bh,
        const float* __restrict__ bias,
        const float* __restrict__ resf,
        const __half* __restrict__ resh, const __half* __restrict__ resl,
        float* __restrict__ C,
        __half* __restrict__ Ch,
        int M, int N, int K)
{
    extern __shared__ char dsm[];
    uint32_t raw = smem_u32(dsm);
    uint32_t tb = (raw + 1023u) & ~1023u;

    const int tid = threadIdx.x;
    const int l   = tid & 31;
    const int wid = tid >> 5;
    const int wm  = (wid & 3) * 32;
    const int wn  = (wid >> 2) * 64;
    const int bm  = blockIdx.x * 128;
    const int bn  = blockIdx.y * 128;

    const uint32_t hi16 = (uint32_t)((l >> 4) * 16);
    uint32_t abase[2], amask[2], bbase[4], bmask[4];
    #pragma unroll
    for (int mi = 0; mi < 2; mi++) {
        uint32_t r = (uint32_t)(wm + mi * 16 + (l & 15));
        abase[mi] = r * 128;
        amask[mi] = (r & 7) << 4;
    }
    #pragma unroll
    for (int nb = 0; nb < 4; nb++) {
        uint32_t r = (uint32_t)(wn + nb * 16 + (l & 15));
        bbase[nb] = r * 128;
        bmask[nb] = (r & 7) << 4;
    }

    float d[2][8][4];
    #pragma unroll
    for (int i = 0; i < 2; i++)
        #pragma unroll
        for (int j = 0; j < 8; j++)
            #pragma unroll
            for (int k = 0; k < 4; k++) d[i][j][k] = 0.f;

    const int nt = K >> 6;

    #define LOAD_T(stg, k0) { \
        uint32_t base = tb + (stg) * STAGE_BYTES; \
        _Pragma("unroll") \
        for (int i = 0; i < 4; i++) { \
            int c = tid + i * 256; int r = c >> 3, s = c & 7; \
            uint32_t off = sw128((uint32_t)(r * 128 + s * 16)); \
            size_t ga = (size_t)(bm + r) * K + (k0) + s * 8; \
            size_t gb = (size_t)(bn + r) * K + (k0) + s * 8; \
            cp16(base + A_HI + off, Ah + ga); \
            cp16(base + B_HI + off, Bh + gb); } }

    LOAD_T(0, 0); CP_COMMIT();

    for (int t = 0; t < nt; t++) {
        CP_WAIT0();                 // stage t resident
        __syncthreads();            // all warps done with stage t-1
        if (t + 1 < nt) {
            LOAD_T((t + 1) & 1, (t + 1) << 6);
            CP_COMMIT();
        }
        {
            uint32_t sb = tb + (uint32_t)(t & 1) * STAGE_BYTES;
            #pragma unroll
            for (int ks = 0; ks < 4; ks++) {
                const uint32_t ko = (uint32_t)(ks * 32);
                uint32_t aH[2][4];
                #pragma unroll
                for (int mi = 0; mi < 2; mi++) {
                    uint32_t ao = abase[mi] + ((hi16 + ko) ^ amask[mi]);
                    ldsm_x4(aH[mi], sb + A_HI + ao);
                }
                uint32_t bH[8][2];
                #pragma unroll
                for (int nb = 0; nb < 4; nb++) {
                    uint32_t bo = bbase[nb] + ((hi16 + ko) ^ bmask[nb]);
                    uint32_t r4[4];
                    ldsm_x4(r4, sb + B_HI + bo);
                    bH[2*nb][0] = r4[0]; bH[2*nb][1] = r4[2];
                    bH[2*nb+1][0] = r4[1]; bH[2*nb+1][1] = r4[3];
                }
                #pragma unroll
                for (int nj = 0; nj < 8; nj++) {
                    #pragma unroll
                    for (int mi = 0; mi < 2; mi++)
                        mma_f16(d[mi][nj], aH[mi], bH[nj]);
                }
            }
        }
    }

    // ---- epilogue ----
    #pragma unroll
    for (int mi = 0; mi < 2; mi++) {
        #pragma unroll
        for (int half = 0; half < 2; half++) {
            int row = bm + wm + mi * 16 + half * 8 + (l >> 2);
            #pragma unroll
            for (int nj = 0; nj < 8; nj++) {
                int col = bn + wn + nj * 8 + 2 * (l & 3);
                float v0 = d[mi][nj][2 * half];
                float v1 = d[mi][nj][2 * half + 1];
                if (bias) { v0 += bias[col]; v1 += bias[col + 1]; }
                size_t ri = (size_t)row * N + col;
                if (RESMODE == 1) {
                    float2 r2 = *(const float2*)&resf[ri];
                    v0 += r2.x; v1 += r2.y;
                } else if (RESMODE == 2) {
                    uint32_t rh = *(const uint32_t*)&resh[ri];
                    uint32_t rl = *(const uint32_t*)&resl[ri];
                    v0 += h2sum(rh, rl, 0);
                    v1 += h2sum(rh, rl, 1);
                }
                if (OUTS) {
                    *(uint32_t*)&Ch[ri] = pack2h(v0, v1);
                } else {
                    float2 o; o.x = v0; o.y = v1;
                    *(float2*)&C[ri] = o;
                }
            }
        }
    }
}

// ================== HMMA flash attention (fp16, hi-only K/V, 2-stage) ==========
#define AQ_HI 0
#define AKV_OFF 16384
#define AKV_BUF 16384           // [Kh 8K][Vh 8K]
#define ATTN_DSMEM (AKV_OFF + 2*AKV_BUF + 1024)

__global__ void __launch_bounds__(256, 2)
attn_mma(const __half* __restrict__ qh, __half* __restrict__ oh)
{
    extern __shared__ char dsm[];
    uint32_t raw = smem_u32(dsm);
    uint32_t tb = (raw + 1023u) & ~1023u;

    const int tid = threadIdx.x;
    const int l   = tid & 31;
    const int w   = tid >> 5;
    const int bh  = blockIdx.y;
    const int b   = bh >> 4;
    const int h   = bh & 15;
    const int q0  = blockIdx.x * 128;
    const size_t hoff = (size_t)h * DH;

    #pragma unroll
    for (int i = 0; i < 4; i++) {
        int lin = tid + i * 256;
        int row = lin >> 3, ch = lin & 7;
        const __half* src = qh + (size_t)(b * SS + q0 + row) * (3 * DD) + hoff + ch * 8;
        cp16(tb + AQ_HI + sw128((uint32_t)(row * 128 + ch * 16)), src);
    }
    #define LOAD_KV(t, buf) { \
        _Pragma("unroll") \
        for (int i = 0; i < 4; i++) { \
            int lin = tid + i * 256; \
            int kv = lin >> 9, row = (lin >> 3) & 63, ch = lin & 7; \
            const __half* src = qh \
                + (size_t)(b * SS + (t) * 64 + row) * (3 * DD) \
                + (kv ? 2 * DD : DD) + hoff + ch * 8; \
            cp16(tb + AKV_OFF + (buf) * AKV_BUF + kv * 8192 \
                 + sw128((uint32_t)(row * 128 + ch * 16)), src); } }

    LOAD_KV(0, 0); CP_COMMIT();

    float od[8][4];
    #pragma unroll
    for (int j = 0; j < 8; j++)
        #pragma unroll
        for (int k = 0; k < 4; k++) od[j][k] = 0.f;
    float m0 = -1e30f, m1 = -1e30f, l0 = 0.f, l1 = 0.f;

    uint32_t aQh[4][4];
    const uint32_t qrow = (uint32_t)(w * 16 + (l & 15));
    const uint32_t qmask = (qrow & 7) << 4;
    const uint32_t hi16 = (uint32_t)((l >> 4) * 16);

    for (int t = 0; t < 16; t++) {
        const int buf = t & 1;
        CP_WAIT0();
        __syncthreads();
        if (t + 1 < 16) { LOAD_KV(t + 1, buf ^ 1); CP_COMMIT(); }
        if (t == 0) {
            #pragma unroll
            for (int ks = 0; ks < 4; ks++) {
                uint32_t off = qrow * 128 + ((hi16 + ks * 32) ^ qmask);
                ldsm_x4(aQh[ks], tb + AQ_HI + off);
            }
        }
        const uint32_t sK = tb + AKV_OFF + buf * AKV_BUF;
        const uint32_t sV = sK + 8192;

        float sc[8][4];
        #pragma unroll
        for (int j = 0; j < 8; j++)
            #pragma unroll
            for (int k = 0; k < 4; k++) sc[j][k] = 0.f;
        #pragma unroll
        for (int ks = 0; ks < 4; ks++) {
            #pragma unroll
            for (int nb = 0; nb < 4; nb++) {
                uint32_t row = (uint32_t)(nb * 16 + (l & 15));
                uint32_t off = row * 128 + ((hi16 + ks * 32) ^ ((row & 7) << 4));
                uint32_t r4[4];
                ldsm_x4(r4, sK + off);
                uint32_t bh0[2] = {r4[0], r4[2]}, bh1[2] = {r4[1], r4[3]};
                mma_f16(sc[2*nb],   aQh[ks], bh0);
                mma_f16(sc[2*nb+1], aQh[ks], bh1);
            }
        }

        float nm0 = m0, nm1 = m1;
        #pragma unroll
        for (int nj = 0; nj < 8; nj++) {
            nm0 = fmaxf(nm0, fmaxf(sc[nj][0], sc[nj][1]));
            nm1 = fmaxf(nm1, fmaxf(sc[nj][2], sc[nj][3]));
        }
        nm0 = fmaxf(nm0, __shfl_xor_sync(0xFFFFFFFFu, nm0, 1));
        nm0 = fmaxf(nm0, __shfl_xor_sync(0xFFFFFFFFu, nm0, 2));
        nm1 = fmaxf(nm1, __shfl_xor_sync(0xFFFFFFFFu, nm1, 1));
        nm1 = fmaxf(nm1, __shfl_xor_sync(0xFFFFFFFFu, nm1, 2));
        float cor0 = __expf(m0 - nm0), cor1 = __expf(m1 - nm1);
        m0 = nm0; m1 = nm1;
        float rs0 = 0.f, rs1 = 0.f;
        #pragma unroll
        for (int nj = 0; nj < 8; nj++) {
            sc[nj][0] = __expf(sc[nj][0] - nm0);
            sc[nj][1] = __expf(sc[nj][1] - nm0);
            sc[nj][2] = __expf(sc[nj][2] - nm1);
            sc[nj][3] = __expf(sc[nj][3] - nm1);
            rs0 += sc[nj][0] + sc[nj][1];
            rs1 += sc[nj][2] + sc[nj][3];
        }
        rs0 += __shfl_xor_sync(0xFFFFFFFFu, rs0, 1);
        rs0 += __shfl_xor_sync(0xFFFFFFFFu, rs0, 2);
        rs1 += __shfl_xor_sync(0xFFFFFFFFu, rs1, 1);
        rs1 += __shfl_xor_sync(0xFFFFFFFFu, rs1, 2);
        l0 = l0 * cor0 + rs0;
        l1 = l1 * cor1 + rs1;
        #pragma unroll
        for (int nj = 0; nj < 8; nj++) {
            od[nj][0] *= cor0; od[nj][1] *= cor0;
            od[nj][2] *= cor1; od[nj][3] *= cor1;
        }

        #pragma unroll
        for (int kj = 0; kj < 4; kj++) {
            uint32_t aPh[4];
            aPh[0] = pack2h(sc[2*kj][0],   sc[2*kj][1]);
            aPh[1] = pack2h(sc[2*kj][2],   sc[2*kj][3]);
            aPh[2] = pack2h(sc[2*kj+1][0], sc[2*kj+1][1]);
            aPh[3] = pack2h(sc[2*kj+1][2], sc[2*kj+1][3]);
            const uint32_t mat = (uint32_t)(l >> 3);
            const uint32_t vrow = (uint32_t)(kj * 16 + (mat & 1) * 8 + (l & 7));
            const uint32_t vmask = (vrow & 7) << 4;
            #pragma unroll
            for (int pp = 0; pp < 4; pp++) {
                uint32_t off = vrow * 128 + (((uint32_t)(pp * 32) + (mat >> 1) * 16) ^ vmask);
                uint32_t rh[4];
                ldsm_x4_t(rh, sV + off);
                uint32_t b0h[2] = {rh[0], rh[1]}, b1h[2] = {rh[2], rh[3]};
                mma_f16(od[2*pp],   aPh, b0h);
                mma_f16(od[2*pp+1], aPh, b1h);
            }
        }
    }

    float inv0 = 1.0f / l0, inv1 = 1.0f / l1;
    int row0 = q0 + w * 16 + (l >> 2);
    #pragma unroll
    for (int nj = 0; nj < 8; nj++) {
        int col = (int)hoff + nj * 8 + 2 * (l & 3);
        size_t ri0 = (size_t)(b * SS + row0) * DD + col;
        size_t ri1 = (size_t)(b * SS + row0 + 8) * DD + col;
        *(uint32_t*)&oh[ri0] = pack2h(od[nj][0] * inv0, od[nj][1] * inv0);
        *(uint32_t*)&oh[ri1] = pack2h(od[nj][2] * inv1, od[nj][3] * inv1);
    }
}

// ---------------- launch -------------------------------------------------------
extern "C" void kernel_launch(void* const* d_in, const int* in_sizes, int n_in,
                              void* d_out, int out_size)
{
    const int*   X     = (const int*)  d_in[0];
    const float* emb   = (const float*)d_in[1];
    const float* pe    = (const float*)d_in[2];
    const float* ln1_g = (const float*)d_in[3];
    const float* ln1_b = (const float*)d_in[4];
    const float* wa    = (const float*)d_in[5];
    const float* ba    = (const float*)d_in[6];
    const float* wp    = (const float*)d_in[7];
    const float* bp    = (const float*)d_in[8];
    const float* ln2_g = (const float*)d_in[9];
    const float* ln2_b = (const float*)d_in[10];
    const float* wf    = (const float*)d_in[11];
    const float* bf    = (const float*)d_in[12];
    const float* wout  = (const float*)d_in[13];
    float* logits = (float*)d_out;

    float *x;
    __half *wh, *qkvh, *hh, *hl, *th, *ah, *xh;
    cudaGetSymbolAddress((void**)&x,    g_x);
    cudaGetSymbolAddress((void**)&wh,   g_wh);
    cudaGetSymbolAddress((void**)&qkvh, g_qkvh);
    cudaGetSymbolAddress((void**)&hh,   g_hh);
    cudaGetSymbolAddress((void**)&hl,   g_hl);
    cudaGetSymbolAddress((void**)&th,   g_th);
    cudaGetSymbolAddress((void**)&ah,   g_ah);
    cudaGetSymbolAddress((void**)&xh,   g_xh);

    cudaFuncSetAttribute(gemm_hh<0,true>,  cudaFuncAttributeMaxDynamicSharedMemorySize, GEMM_DSMEM);
    cudaFuncSetAttribute(gemm_hh<2,false>, cudaFuncAttributeMaxDynamicSharedMemorySize, GEMM_DSMEM);
    cudaFuncSetAttribute(gemm_hh<1,false>, cudaFuncAttributeMaxDynamicSharedMemorySize, GEMM_DSMEM);
    cudaFuncSetAttribute(gemm_hh<1,true>,  cudaFuncAttributeMaxDynamicSharedMemorySize, GEMM_DSMEM);
    cudaFuncSetAttribute(gemm_hh<0,false>, cudaFuncAttributeMaxDynamicSharedMemorySize, GEMM_DSMEM);
    cudaFuncSetAttribute(attn_mma, cudaFuncAttributeMaxDynamicSharedMemorySize, ATTN_DSMEM);

    // weight prep (per replay, HBM-stream bound; fp16 hi only)
    transpose_tohalf_kernel<<<dim3(3*DD/32, DD/32, LL), dim3(32,8)>>>(
        wa, wh + WA_T_OFF, DD, 3*DD);
    transpose_tohalf_kernel<<<dim3(DD/32, DD/32, LL), dim3(32,8)>>>(
        wp, wh + WP_T_OFF, DD, DD);
    transpose_tohalf_kernel<<<dim3(DD/32, DD/32, LL), dim3(32,8)>>>(
        wf, wh + WF_T_OFF, DD, DD);
    tohalf_kernel<<<(VV*1024/4)/256, 256>>>(wout, wh + WOUT_OFF);

    embed_kernel<<<NTOK, 256>>>(X, emb, pe, x);

    for (int i = 0; i < LL; i++) {
        const float* ba_i = ba + (size_t)i * 3 * DD;
        const float* bp_i = bp + (size_t)i * DD;
        const float* bf_i = bf + (size_t)i * DD;
        const __half* wa_h = wh + WA_T_OFF + (size_t)i * 3*DD * DD;
        const __half* wp_h = wh + WP_T_OFF + (size_t)i * DD * DD;
        const __half* wf_h = wh + WF_T_OFF + (size_t)i * DD * DD;

        // h = LN1(x) -> fp16 pair (warp-per-row)
        ln_w_kernel<true><<<NTOK/8, 256>>>(x, ln1_g + (size_t)i * DD, ln1_b + (size_t)i * DD, hh, hl);
        // qkv = h @ wa + ba -> fp16 hi
        gemm_hh<0,true><<<dim3(NTOK/128, 3*DD/128), 256, GEMM_DSMEM>>>(
            hh, wa_h, ba_i, nullptr, nullptr, nullptr,
            nullptr, qkvh, NTOK, 3*DD, DD);
        attn_mma<<<dim3(SS/128, BB*HH), 256, ATTN_DSMEM>>>(qkvh, ah);
        // x = h + attn @ wp + bp
        gemm_hh<2,false><<<dim3(NTOK/128, DD/128), 256, GEMM_DSMEM>>>(
            ah, wp_h, bp_i, nullptr, hh, hl,
            x, nullptr, NTOK, DD, DD);
        // tmp = LN2(x) -> fp16 hi (warp-per-row)
        ln_w_kernel<false><<<NTOK/8, 256>>>(x, ln2_g + (size_t)i * DD, ln2_b + (size_t)i * DD, th, nullptr);
        // x = x + tmp @ wf + bf ; last layer emits xh fp16 directly (x dead after)
        if (i + 1 < LL) {
            gemm_hh<1,false><<<dim3(NTOK/128, DD/128), 256, GEMM_DSMEM>>>(
                th, wf_h, bf_i, x, nullptr, nullptr,
                x, nullptr, NTOK, DD, DD);
        } else {
            gemm_hh<1,true><<<dim3(NTOK/128, DD/128), 256, GEMM_DSMEM>>>(
                th, wf_h, bf_i, x, nullptr, nullptr,
                nullptr, xh, NTOK, DD, DD);
        }
    }

    // logits = x @ wout^T
    gemm_hh<0,false><<<dim3(NTOK/128, VV/128), 256, GEMM_DSMEM>>>(
        xh, wh + WOUT_OFF, nullptr, nullptr, nullptr, nullptr,
        logits, nullptr, NTOK, VV, DD);
    (void)in_sizes; (void)n_in; (void)out_size;
}